// round 12
// baseline (speedup 1.0000x reference)
#include <cuda_runtime.h>
#include <cuda_fp16.h>
#include <stdint.h>

// EdgeHead via warp-level mma.sync (HMMA fp16), raw-feature A operand:
// LN folded OUT of the GEMM:  sum_k z_k W'_kj = rs*(sum_k feat_k W'_kj)
//                                             - rs*mu*(sum_k W'_kj)
// so A = [u, v, |u-v|, u*v] raw fp16 (u,v stored half2; d,p one op per t),
// and the affine (rs, rs*mu, colsum, bc) is applied per-column in the fp32
// epilogue. B = (gamma.*W1)^T fp16 in smem (k-permuted + XOR-swizzled).
// bc = beta @ W1 + b1, colsum_j = sum_k gamma_k W1_kj.
// 6 CTAs/SM (24 warps) via 85-reg budget.

#define NTHREADS 128
typedef unsigned long long u64;

__device__ __forceinline__ u64 pk2(float x, float y) {
    u64 r; asm("mov.b64 %0, {%1, %2};" : "=l"(r) : "f"(x), "f"(y)); return r;
}
__device__ __forceinline__ void upk2(u64 a, float& x, float& y) {
    asm("mov.b64 {%0, %1}, %2;" : "=f"(x), "=f"(y) : "l"(a));
}
__device__ __forceinline__ u64 fma2(u64 a, u64 b, u64 c) {
    u64 r; asm("fma.rn.f32x2 %0, %1, %2, %3;" : "=l"(r) : "l"(a), "l"(b), "l"(c));
    return r;
}
__device__ __forceinline__ u64 add2(u64 a, u64 b) {
    u64 r; asm("add.rn.f32x2 %0, %1, %2;" : "=l"(r) : "l"(a), "l"(b)); return r;
}
__device__ __forceinline__ u64 mul2(u64 a, u64 b) {
    u64 r; asm("mul.rn.f32x2 %0, %1, %2;" : "=l"(r) : "l"(a), "l"(b)); return r;
}
#define ABS2MASK 0x7fffffff7fffffffULL

__device__ __forceinline__ uint32_t pack_h2(float x, float y) {
    __half2 t = __floats2half2_rn(x, y);   // .x = low half
    uint32_t r; memcpy(&r, &t, 4); return r;
}
__device__ __forceinline__ __half2 u2h(uint32_t u) {
    __half2 t; memcpy(&t, &u, 4); return t;
}
__device__ __forceinline__ uint32_t h2u(__half2 h) {
    uint32_t r; memcpy(&r, &h, 4); return r;
}

__device__ __forceinline__ void mma16816(float* c, uint32_t a0, uint32_t a1,
                                         uint32_t a2, uint32_t a3,
                                         uint32_t b0, uint32_t b1) {
    asm volatile(
        "mma.sync.aligned.m16n8k16.row.col.f32.f16.f16.f32 "
        "{%0,%1,%2,%3}, {%4,%5,%6,%7}, {%8,%9}, {%0,%1,%2,%3};"
        : "+f"(c[0]), "+f"(c[1]), "+f"(c[2]), "+f"(c[3])
        : "r"(a0), "r"(a1), "r"(a2), "r"(a3), "r"(b0), "r"(b1));
}

__device__ __forceinline__ void ldsm4(uint32_t addr, uint32_t& r0, uint32_t& r1,
                                      uint32_t& r2, uint32_t& r3) {
    asm volatile("ldmatrix.sync.aligned.m8n8.x4.shared.b16 {%0,%1,%2,%3}, [%4];"
                 : "=r"(r0), "=r"(r1), "=r"(r2), "=r"(r3) : "r"(addr));
}

// stats accumulate for one packed (u,v) pair into S1,S2 (fp32 exact)
__device__ __forceinline__ void statacc(u64 uu, u64 vv, u64 neg1,
                                        u64& S1, u64& S2) {
    const u64 p = mul2(uu, vv);
    const u64 d = fma2(vv, neg1, uu) & ABS2MASK;
    S1 = add2(S1, add2(uu, vv));
    S1 = add2(S1, add2(d, p));
    S2 = fma2(uu, uu, S2); S2 = fma2(vv, vv, S2);
    S2 = fma2(d, d, S2);   S2 = fma2(p, p, S2);
}

__global__ __launch_bounds__(NTHREADS, 6)
void edgehead_mma(const float* __restrict__ h,
                  const void* __restrict__ ep_raw,
                  const float* __restrict__ gamma,
                  const float* __restrict__ beta,
                  const float* __restrict__ W1,
                  const float* __restrict__ b1,
                  const float* __restrict__ W2,
                  const float* __restrict__ b2,
                  float* __restrict__ out,
                  int E, int nGroups)
{
    __shared__ __align__(128) unsigned char Bhi[16384];  // 32j x 256k fp16, swz
    __shared__ float bc_s[32], w2_s[32], cs_s[32];

    const int tid = threadIdx.x;
    const int wid = tid >> 5;
    const int lane = tid & 31;

    // ---- stage B^T = (gamma .* W1)^T fp16, k-permuted + XOR-swizzled ----
    // phys k within 16-block maps to mma col m = ((k&12)>>1) + ((k&2)?8:0)
    for (int p = tid; p < 4096; p += NTHREADS) {
        const int j = p & 31;
        const int k0 = (p >> 5) << 1;                    // even phys k
        const float w0 = gamma[k0] * W1[k0 * 32 + j];
        const float w1 = gamma[k0 + 1] * W1[(k0 + 1) * 32 + j];
        const int m0 = ((k0 & 12) >> 1) + ((k0 & 2) ? 8 : 0);
        const int kp = (k0 & ~15) + m0;                  // permuted, even
        const uint32_t off = (uint32_t)(j * 512 + ((((kp >> 3)) ^ (j & 7)) << 4)
                                        + (kp & 7) * 2);
        *(uint32_t*)(Bhi + off) = pack_h2(w0, w1);
    }
    if (tid < 32) {
        float ab = b1[tid];     // bc = beta @ W1 + b1
        float ac = 0.f;         // colsum = gamma @ W1 (columnwise)
        #pragma unroll 8
        for (int k = 0; k < 256; k++) {
            const float w = W1[k * 32 + tid];
            ab = fmaf(beta[k], w, ab);
            ac = fmaf(gamma[k], w, ac);
        }
        bc_s[tid] = ab;
        cs_s[tid] = ac;
        w2_s[tid] = W2[tid];
    }
    __syncthreads();

    // ---- edge index dtype sniff (int64 vs int32) ----
    const int* ep32 = (const int*)ep_raw;
    const long long* ep64 = (const long long*)ep_raw;
    int hiOr = 0;
    #pragma unroll
    for (int t = 1; t < 16; t += 2) hiOr |= ep32[t];
    const bool wide = (hiOr == 0);
    const float b2v = b2[0];
    const u64 neg1 = pk2(-1.f, -1.f);

    // ---- per-lane constants ----
    const int cq = lane & 3;           // quad position: owns phys dims 4cq..+3
    const int q = lane >> 2;           // edge row within group (and +8)
    const float4* __restrict__ hv4 = (const float4*)h;   // 16 float4 per node

    const int x7 = lane & 7;
    const int pday = (lane >> 3) & 1;
    const int jrow = ((lane >> 4)) * 8 + x7;
    const uint32_t bhiB = (uint32_t)__cvta_generic_to_shared(Bhi) + jrow * 512;

    const int gw = blockIdx.x * (NTHREADS / 32) + wid;
    const int gstride = gridDim.x * (NTHREADS / 32);

    for (int g = gw; g < nGroups; g += gstride) {
        const int e0 = g * 16 + q;
        const int e1 = e0 + 8;
        const bool v0 = e0 < E, v1 = e1 < E;
        int s0, d0, s1i, d1;
        if (wide) {
            s0 = v0 ? (int)ep64[e0] : 0; d0 = v0 ? (int)ep64[e0 + E] : 0;
            s1i = v1 ? (int)ep64[e1] : 0; d1 = v1 ? (int)ep64[e1 + E] : 0;
        } else {
            s0 = v0 ? ep32[e0] : 0; d0 = v0 ? ep32[e0 + E] : 0;
            s1i = v1 ? ep32[e1] : 0; d1 = v1 ? ep32[e1 + E] : 0;
        }

        // ---- gather + inline stats (fp32) + compress raws to half2 ----
        uint32_t Uh0[8], Vh0[8], Uh1[8], Vh1[8];   // 32 regs total
        u64 S1a = 0, S2a = 0, S1b = 0, S2b = 0;
        {
            const float4* pu0 = hv4 + (s0 * 16 + cq);
            const float4* pv0 = hv4 + (d0 * 16 + cq);
            const float4* pu1 = hv4 + (s1i * 16 + cq);
            const float4* pv1 = hv4 + (d1 * 16 + cq);
            #pragma unroll
            for (int t = 0; t < 4; t++) {
                const float4 a = pu0[4 * t];
                const float4 b = pv0[4 * t];
                const float4 c = pu1[4 * t];
                const float4 d = pv1[4 * t];
                statacc(pk2(a.x, a.y), pk2(b.x, b.y), neg1, S1a, S2a);
                statacc(pk2(a.z, a.w), pk2(b.z, b.w), neg1, S1a, S2a);
                statacc(pk2(c.x, c.y), pk2(d.x, d.y), neg1, S1b, S2b);
                statacc(pk2(c.z, c.w), pk2(d.z, d.w), neg1, S1b, S2b);
                Uh0[2*t] = pack_h2(a.x, a.y); Uh0[2*t+1] = pack_h2(a.z, a.w);
                Vh0[2*t] = pack_h2(b.x, b.y); Vh0[2*t+1] = pack_h2(b.z, b.w);
                Uh1[2*t] = pack_h2(c.x, c.y); Uh1[2*t+1] = pack_h2(c.z, c.w);
                Vh1[2*t] = pack_h2(d.x, d.y); Vh1[2*t+1] = pack_h2(d.z, d.w);
            }
        }
        float s1r0, s2r0, s1r1, s2r1, tx, ty;
        upk2(S1a, tx, ty); s1r0 = tx + ty;
        upk2(S2a, tx, ty); s2r0 = tx + ty;
        upk2(S1b, tx, ty); s1r1 = tx + ty;
        upk2(S2b, tx, ty); s2r1 = tx + ty;

        s1r0 += __shfl_xor_sync(0xffffffffu, s1r0, 1);
        s1r0 += __shfl_xor_sync(0xffffffffu, s1r0, 2);
        s2r0 += __shfl_xor_sync(0xffffffffu, s2r0, 1);
        s2r0 += __shfl_xor_sync(0xffffffffu, s2r0, 2);
        s1r1 += __shfl_xor_sync(0xffffffffu, s1r1, 1);
        s1r1 += __shfl_xor_sync(0xffffffffu, s1r1, 2);
        s2r1 += __shfl_xor_sync(0xffffffffu, s2r1, 1);
        s2r1 += __shfl_xor_sync(0xffffffffu, s2r1, 2);

        const float mu0 = s1r0 * (1.f / 256.f);
        const float rs0 = rsqrtf(fmaf(-mu0, mu0, s2r0 * (1.f / 256.f)) + 1e-5f);
        const float mu1 = s1r1 * (1.f / 256.f);
        const float rs1 = rsqrtf(fmaf(-mu1, mu1, s2r1 * (1.f / 256.f)) + 1e-5f);

        float acc[4][4];
        #pragma unroll
        for (int nt = 0; nt < 4; nt++)
            #pragma unroll
            for (int rr = 0; rr < 4; rr++) acc[nt][rr] = 0.f;

        // ---- mma loop: raw-feature A operands; t outer, s inner ----
        #pragma unroll
        for (int t = 0; t < 4; t++) {
            // per-t derived features (one op each, reused across s)
            const uint32_t d0l = h2u(__habs2(__hsub2(u2h(Uh0[2*t]),   u2h(Vh0[2*t]))));
            const uint32_t d0h = h2u(__habs2(__hsub2(u2h(Uh0[2*t+1]), u2h(Vh0[2*t+1]))));
            const uint32_t d1l = h2u(__habs2(__hsub2(u2h(Uh1[2*t]),   u2h(Vh1[2*t]))));
            const uint32_t d1h = h2u(__habs2(__hsub2(u2h(Uh1[2*t+1]), u2h(Vh1[2*t+1]))));
            const uint32_t p0l = h2u(__hmul2(u2h(Uh0[2*t]),   u2h(Vh0[2*t])));
            const uint32_t p0h = h2u(__hmul2(u2h(Uh0[2*t+1]), u2h(Vh0[2*t+1])));
            const uint32_t p1l = h2u(__hmul2(u2h(Uh1[2*t]),   u2h(Vh1[2*t])));
            const uint32_t p1h = h2u(__hmul2(u2h(Uh1[2*t+1]), u2h(Vh1[2*t+1])));

            #pragma unroll
            for (int s = 0; s < 4; s++) {
                const int ks = s * 4 + t;
                uint32_t a0, a1, a2, a3;   // {row q klo, row q+8 klo, row q khi, row q+8 khi}
                if (s == 0)      { a0 = Uh0[2*t]; a1 = Uh1[2*t]; a2 = Uh0[2*t+1]; a3 = Uh1[2*t+1]; }
                else if (s == 1) { a0 = Vh0[2*t]; a1 = Vh1[2*t]; a2 = Vh0[2*t+1]; a3 = Vh1[2*t+1]; }
                else if (s == 2) { a0 = d0l;      a1 = d1l;      a2 = d0h;        a3 = d1h; }
                else             { a0 = p0l;      a1 = p1l;      a2 = p0h;        a3 = p1h; }

                const uint32_t sw = (uint32_t)((((ks * 2 + pday) ^ x7)) << 4);
                uint32_t bh[8];
                ldsm4(bhiB + sw,        bh[0], bh[1], bh[2], bh[3]);   // nt 0,1
                ldsm4(bhiB + sw + 8192, bh[4], bh[5], bh[6], bh[7]);   // nt 2,3

                #pragma unroll
                for (int nt = 0; nt < 4; nt++)
                    mma16816(acc[nt], a0, a1, a2, a3, bh[2 * nt], bh[2 * nt + 1]);
            }
        }

        // ---- epilogue: LN affine + relu + W2 dot, quad reduce ----
        // hm_j = rs*acc_j - rs*mu*colsum_j + bc_j
        const float rm0 = rs0 * mu0, rm1 = rs1 * mu1;
        const int c = cq * 2;
        float pp0 = 0.f, pp1 = 0.f;
        #pragma unroll
        for (int nt = 0; nt < 4; nt++) {
            const float bcx = bc_s[nt * 8 + c], bcy = bc_s[nt * 8 + c + 1];
            const float w2x = w2_s[nt * 8 + c], w2y = w2_s[nt * 8 + c + 1];
            const float csx = cs_s[nt * 8 + c], csy = cs_s[nt * 8 + c + 1];
            pp0 = fmaf(fmaxf(fmaf(rs0, acc[nt][0], fmaf(-rm0, csx, bcx)), 0.f), w2x, pp0);
            pp0 = fmaf(fmaxf(fmaf(rs0, acc[nt][1], fmaf(-rm0, csy, bcy)), 0.f), w2y, pp0);
            pp1 = fmaf(fmaxf(fmaf(rs1, acc[nt][2], fmaf(-rm1, csx, bcx)), 0.f), w2x, pp1);
            pp1 = fmaf(fmaxf(fmaf(rs1, acc[nt][3], fmaf(-rm1, csy, bcy)), 0.f), w2y, pp1);
        }
        pp0 += __shfl_xor_sync(0xffffffffu, pp0, 1);
        pp0 += __shfl_xor_sync(0xffffffffu, pp0, 2);
        pp1 += __shfl_xor_sync(0xffffffffu, pp1, 1);
        pp1 += __shfl_xor_sync(0xffffffffu, pp1, 2);
        if (cq == 0) {
            if (v0) out[e0] = pp0 + b2v;
            if (v1) out[e1] = pp1 + b2v;
        }
    }
}

extern "C" void kernel_launch(void* const* d_in, const int* in_sizes, int n_in,
                              void* d_out, int out_size)
{
    const float* h     = (const float*)d_in[0];
    const void*  ep    = d_in[1];
    const float* gamma = (const float*)d_in[2];
    const float* beta  = (const float*)d_in[3];
    const float* W1    = (const float*)d_in[4];
    const float* b1    = (const float*)d_in[5];
    const float* W2    = (const float*)d_in[6];
    const float* b2    = (const float*)d_in[7];
    float* out = (float*)d_out;
    const int E = out_size;
    const int nGroups = (E + 15) / 16;

    int dev = 0, sms = 148;
    cudaGetDevice(&dev);
    cudaDeviceGetAttribute(&sms, cudaDevAttrMultiProcessorCount, dev);
    int grid = sms * 6;
    const int maxg = (nGroups + (NTHREADS / 32) - 1) / (NTHREADS / 32);
    if (grid > maxg) grid = maxg;

    edgehead_mma<<<grid, NTHREADS>>>(h, ep, gamma, beta, W1, b1, W2, b2,
                                     out, E, nGroups);
}

// round 13
// speedup vs baseline: 1.0038x; 1.0038x over previous
#include <cuda_runtime.h>
#include <cuda_fp16.h>
#include <stdint.h>

// EdgeHead via warp-level mma.sync (HMMA fp16), M=32 edges/warp:
// two m16n8k16 M-tiles share every ldmatrix'd B fragment, cutting L1
// wavefronts from 16/edge to 12/edge (LDSM amortized). Raw-feature A:
// LN folded OUT of the GEMM:  sum_k z_k W'_kj = rs*(sum_k feat_k W'_kj)
//                                             - rs*mu*(sum_k W'_kj)
// A = [u, v, |u-v|, u*v] raw fp16 (u,v stored half2; d,p computed at use).
// Epilogue applies rs/mu/colsum/bc per column in fp32.
// B = (gamma.*W1)^T fp16 smem, k-permuted + XOR-swizzled.

#define NTHREADS 128
typedef unsigned long long u64;

__device__ __forceinline__ u64 pk2(float x, float y) {
    u64 r; asm("mov.b64 %0, {%1, %2};" : "=l"(r) : "f"(x), "f"(y)); return r;
}
__device__ __forceinline__ void upk2(u64 a, float& x, float& y) {
    asm("mov.b64 {%0, %1}, %2;" : "=f"(x), "=f"(y) : "l"(a));
}
__device__ __forceinline__ u64 fma2(u64 a, u64 b, u64 c) {
    u64 r; asm("fma.rn.f32x2 %0, %1, %2, %3;" : "=l"(r) : "l"(a), "l"(b), "l"(c));
    return r;
}
__device__ __forceinline__ u64 add2(u64 a, u64 b) {
    u64 r; asm("add.rn.f32x2 %0, %1, %2;" : "=l"(r) : "l"(a), "l"(b)); return r;
}
__device__ __forceinline__ u64 mul2(u64 a, u64 b) {
    u64 r; asm("mul.rn.f32x2 %0, %1, %2;" : "=l"(r) : "l"(a), "l"(b)); return r;
}
#define ABS2MASK 0x7fffffff7fffffffULL

__device__ __forceinline__ uint32_t pack_h2(float x, float y) {
    __half2 t = __floats2half2_rn(x, y);   // .x = low half
    uint32_t r; memcpy(&r, &t, 4); return r;
}
__device__ __forceinline__ __half2 u2h(uint32_t u) {
    __half2 t; memcpy(&t, &u, 4); return t;
}
__device__ __forceinline__ uint32_t h2u(__half2 h) {
    uint32_t r; memcpy(&r, &h, 4); return r;
}

__device__ __forceinline__ void mma16816(float* c, uint32_t a0, uint32_t a1,
                                         uint32_t a2, uint32_t a3,
                                         uint32_t b0, uint32_t b1) {
    asm volatile(
        "mma.sync.aligned.m16n8k16.row.col.f32.f16.f16.f32 "
        "{%0,%1,%2,%3}, {%4,%5,%6,%7}, {%8,%9}, {%0,%1,%2,%3};"
        : "+f"(c[0]), "+f"(c[1]), "+f"(c[2]), "+f"(c[3])
        : "r"(a0), "r"(a1), "r"(a2), "r"(a3), "r"(b0), "r"(b1));
}

__device__ __forceinline__ void ldsm4(uint32_t addr, uint32_t& r0, uint32_t& r1,
                                      uint32_t& r2, uint32_t& r3) {
    asm volatile("ldmatrix.sync.aligned.m8n8.x4.shared.b16 {%0,%1,%2,%3}, [%4];"
                 : "=r"(r0), "=r"(r1), "=r"(r2), "=r"(r3) : "r"(addr));
}

// raw-feature A fragment register for segment s (free select for s=0,1)
__device__ __forceinline__ uint32_t afrag(int s, uint32_t u, uint32_t v) {
    if (s == 0) return u;
    if (s == 1) return v;
    if (s == 2) return h2u(__habs2(__hsub2(u2h(u), u2h(v))));
    return h2u(__hmul2(u2h(u), u2h(v)));
}

// gather one edge-row (u,v nodes) + fp32 stats + compress to half2
__device__ __forceinline__ void gather_row(
    const float4* __restrict__ hv4, int src, int dst, int cq, u64 neg1,
    uint32_t* Uh, uint32_t* Vh, float& s1o, float& s2o)
{
    const float4* pu = hv4 + (src * 16 + cq);
    const float4* pv = hv4 + (dst * 16 + cq);
    u64 S1 = 0, S2 = 0;
    #pragma unroll
    for (int t = 0; t < 4; t++) {
        const float4 a = pu[4 * t];
        const float4 b = pv[4 * t];
        #pragma unroll
        for (int hlf = 0; hlf < 2; hlf++) {
            const u64 uu = hlf ? pk2(a.z, a.w) : pk2(a.x, a.y);
            const u64 vv = hlf ? pk2(b.z, b.w) : pk2(b.x, b.y);
            const u64 p = mul2(uu, vv);
            const u64 d = fma2(vv, neg1, uu) & ABS2MASK;
            S1 = add2(S1, add2(uu, vv));
            S1 = add2(S1, add2(d, p));
            S2 = fma2(uu, uu, S2); S2 = fma2(vv, vv, S2);
            S2 = fma2(d, d, S2);   S2 = fma2(p, p, S2);
        }
        Uh[2*t] = pack_h2(a.x, a.y); Uh[2*t+1] = pack_h2(a.z, a.w);
        Vh[2*t] = pack_h2(b.x, b.y); Vh[2*t+1] = pack_h2(b.z, b.w);
    }
    float x, y;
    upk2(S1, x, y); s1o = x + y;
    upk2(S2, x, y); s2o = x + y;
}

__global__ __launch_bounds__(NTHREADS, 4)
void edgehead_mma(const float* __restrict__ h,
                  const void* __restrict__ ep_raw,
                  const float* __restrict__ gamma,
                  const float* __restrict__ beta,
                  const float* __restrict__ W1,
                  const float* __restrict__ b1,
                  const float* __restrict__ W2,
                  const float* __restrict__ b2,
                  float* __restrict__ out,
                  int E, int nGroups)
{
    __shared__ __align__(128) unsigned char Bhi[16384];  // 32j x 256k fp16, swz
    __shared__ float bc_s[32], w2_s[32], cs_s[32];

    const int tid = threadIdx.x;
    const int wid = tid >> 5;
    const int lane = tid & 31;

    // ---- stage B^T = (gamma .* W1)^T fp16, k-permuted + XOR-swizzled ----
    // phys k within 16-block maps to mma col m = ((k&12)>>1) + ((k&2)?8:0)
    for (int p = tid; p < 4096; p += NTHREADS) {
        const int j = p & 31;
        const int k0 = (p >> 5) << 1;                    // even phys k
        const float w0 = gamma[k0] * W1[k0 * 32 + j];
        const float w1 = gamma[k0 + 1] * W1[(k0 + 1) * 32 + j];
        const int m0 = ((k0 & 12) >> 1) + ((k0 & 2) ? 8 : 0);
        const int kp = (k0 & ~15) + m0;                  // permuted, even
        const uint32_t off = (uint32_t)(j * 512 + ((((kp >> 3)) ^ (j & 7)) << 4)
                                        + (kp & 7) * 2);
        *(uint32_t*)(Bhi + off) = pack_h2(w0, w1);
    }
    if (tid < 32) {
        float ab = b1[tid];     // bc = beta @ W1 + b1
        float ac = 0.f;         // colsum = gamma @ W1 (columnwise)
        #pragma unroll 8
        for (int k = 0; k < 256; k++) {
            const float w = W1[k * 32 + tid];
            ab = fmaf(beta[k], w, ab);
            ac = fmaf(gamma[k], w, ac);
        }
        bc_s[tid] = ab;
        cs_s[tid] = ac;
        w2_s[tid] = W2[tid];
    }
    __syncthreads();

    // ---- edge index dtype sniff (int64 vs int32) ----
    const int* ep32 = (const int*)ep_raw;
    const long long* ep64 = (const long long*)ep_raw;
    int hiOr = 0;
    #pragma unroll
    for (int t = 1; t < 16; t += 2) hiOr |= ep32[t];
    const bool wide = (hiOr == 0);
    const float b2v = b2[0];
    const u64 neg1 = pk2(-1.f, -1.f);

    // ---- per-lane constants ----
    const int cq = lane & 3;           // quad position: owns phys dims 4cq..+3
    const int q = lane >> 2;           // edge row within group
    const float4* __restrict__ hv4 = (const float4*)h;   // 16 float4 per node

    const int x7 = lane & 7;
    const int pday = (lane >> 3) & 1;
    const int jrow = ((lane >> 4)) * 8 + x7;
    const uint32_t bhiB = (uint32_t)__cvta_generic_to_shared(Bhi) + jrow * 512;

    const int gw = blockIdx.x * (NTHREADS / 32) + wid;
    const int gstride = gridDim.x * (NTHREADS / 32);

    for (int g = gw; g < nGroups; g += gstride) {
        // 4 edge rows per lane: e0=q, e1=q+8 (tile0); e2=q+16, e3=q+24 (tile1)
        const int eb = g * 32 + q;
        int srcs[4], dsts[4];
        #pragma unroll
        for (int r = 0; r < 4; r++) {
            const int e = eb + r * 8;
            const bool v = e < E;
            if (wide) { srcs[r] = v ? (int)ep64[e] : 0;
                        dsts[r] = v ? (int)ep64[e + E] : 0; }
            else      { srcs[r] = v ? ep32[e] : 0;
                        dsts[r] = v ? ep32[e + E] : 0; }
        }

        // ---- gather + inline stats + compress (4 rows) ----
        uint32_t Uh0[8], Vh0[8], Uh1[8], Vh1[8];
        uint32_t Uh2[8], Vh2[8], Uh3[8], Vh3[8];
        float s1r[4], s2r[4];
        gather_row(hv4, srcs[0], dsts[0], cq, neg1, Uh0, Vh0, s1r[0], s2r[0]);
        gather_row(hv4, srcs[1], dsts[1], cq, neg1, Uh1, Vh1, s1r[1], s2r[1]);
        gather_row(hv4, srcs[2], dsts[2], cq, neg1, Uh2, Vh2, s1r[2], s2r[2]);
        gather_row(hv4, srcs[3], dsts[3], cq, neg1, Uh3, Vh3, s1r[3], s2r[3]);

        float rs[4], rm[4];
        #pragma unroll
        for (int r = 0; r < 4; r++) {
            float s1 = s1r[r], s2 = s2r[r];
            s1 += __shfl_xor_sync(0xffffffffu, s1, 1);
            s1 += __shfl_xor_sync(0xffffffffu, s1, 2);
            s2 += __shfl_xor_sync(0xffffffffu, s2, 1);
            s2 += __shfl_xor_sync(0xffffffffu, s2, 2);
            const float mu = s1 * (1.f / 256.f);
            const float rsv = rsqrtf(fmaf(-mu, mu, s2 * (1.f / 256.f)) + 1e-5f);
            rs[r] = rsv;
            rm[r] = rsv * mu;
        }

        float acc0[4][4], acc1[4][4];
        #pragma unroll
        for (int nt = 0; nt < 4; nt++)
            #pragma unroll
            for (int rr = 0; rr < 4; rr++) { acc0[nt][rr] = 0.f; acc1[nt][rr] = 0.f; }

        // ---- mma loop: 2 M-tiles share each B fragment ----
        #pragma unroll
        for (int t = 0; t < 4; t++) {
            #pragma unroll
            for (int s = 0; s < 4; s++) {
                const int ks = s * 4 + t;
                const uint32_t sw = (uint32_t)((((ks * 2 + pday) ^ x7)) << 4);
                uint32_t bh[8];
                ldsm4(bhiB + sw,        bh[0], bh[1], bh[2], bh[3]);   // nt 0,1
                ldsm4(bhiB + sw + 8192, bh[4], bh[5], bh[6], bh[7]);   // nt 2,3

                const uint32_t a00 = afrag(s, Uh0[2*t],   Vh0[2*t]);
                const uint32_t a01 = afrag(s, Uh1[2*t],   Vh1[2*t]);
                const uint32_t a02 = afrag(s, Uh0[2*t+1], Vh0[2*t+1]);
                const uint32_t a03 = afrag(s, Uh1[2*t+1], Vh1[2*t+1]);
                const uint32_t a10 = afrag(s, Uh2[2*t],   Vh2[2*t]);
                const uint32_t a11 = afrag(s, Uh3[2*t],   Vh3[2*t]);
                const uint32_t a12 = afrag(s, Uh2[2*t+1], Vh2[2*t+1]);
                const uint32_t a13 = afrag(s, Uh3[2*t+1], Vh3[2*t+1]);

                #pragma unroll
                for (int nt = 0; nt < 4; nt++) {
                    mma16816(acc0[nt], a00, a01, a02, a03, bh[2*nt], bh[2*nt+1]);
                    mma16816(acc1[nt], a10, a11, a12, a13, bh[2*nt], bh[2*nt+1]);
                }
            }
        }

        // ---- epilogue: LN affine + relu + W2 dot, quad reduce, 4 outputs ----
        // hm_j = rs*acc_j - rs*mu*colsum_j + bc_j
        const int c = cq * 2;
        float pp[4] = {0.f, 0.f, 0.f, 0.f};
        #pragma unroll
        for (int nt = 0; nt < 4; nt++) {
            const float bcx = bc_s[nt * 8 + c], bcy = bc_s[nt * 8 + c + 1];
            const float w2x = w2_s[nt * 8 + c], w2y = w2_s[nt * 8 + c + 1];
            const float csx = cs_s[nt * 8 + c], csy = cs_s[nt * 8 + c + 1];
            pp[0] = fmaf(fmaxf(fmaf(rs[0], acc0[nt][0], fmaf(-rm[0], csx, bcx)), 0.f), w2x, pp[0]);
            pp[0] = fmaf(fmaxf(fmaf(rs[0], acc0[nt][1], fmaf(-rm[0], csy, bcy)), 0.f), w2y, pp[0]);
            pp[1] = fmaf(fmaxf(fmaf(rs[1], acc0[nt][2], fmaf(-rm[1], csx, bcx)), 0.f), w2x, pp[1]);
            pp[1] = fmaf(fmaxf(fmaf(rs[1], acc0[nt][3], fmaf(-rm[1], csy, bcy)), 0.f), w2y, pp[1]);
            pp[2] = fmaf(fmaxf(fmaf(rs[2], acc1[nt][0], fmaf(-rm[2], csx, bcx)), 0.f), w2x, pp[2]);
            pp[2] = fmaf(fmaxf(fmaf(rs[2], acc1[nt][1], fmaf(-rm[2], csy, bcy)), 0.f), w2y, pp[2]);
            pp[3] = fmaf(fmaxf(fmaf(rs[3], acc1[nt][2], fmaf(-rm[3], csx, bcx)), 0.f), w2x, pp[3]);
            pp[3] = fmaf(fmaxf(fmaf(rs[3], acc1[nt][3], fmaf(-rm[3], csy, bcy)), 0.f), w2y, pp[3]);
        }
        #pragma unroll
        for (int r = 0; r < 4; r++) {
            float v = pp[r];
            v += __shfl_xor_sync(0xffffffffu, v, 1);
            v += __shfl_xor_sync(0xffffffffu, v, 2);
            if (cq == 0) {
                const int e = eb + r * 8;
                if (e < E) out[e] = v + b2v;
            }
        }
    }
}

extern "C" void kernel_launch(void* const* d_in, const int* in_sizes, int n_in,
                              void* d_out, int out_size)
{
    const float* h     = (const float*)d_in[0];
    const void*  ep    = d_in[1];
    const float* gamma = (const float*)d_in[2];
    const float* beta  = (const float*)d_in[3];
    const float* W1    = (const float*)d_in[4];
    const float* b1    = (const float*)d_in[5];
    const float* W2    = (const float*)d_in[6];
    const float* b2    = (const float*)d_in[7];
    float* out = (float*)d_out;
    const int E = out_size;
    const int nGroups = (E + 31) / 32;

    int dev = 0, sms = 148;
    cudaGetDevice(&dev);
    cudaDeviceGetAttribute(&sms, cudaDevAttrMultiProcessorCount, dev);
    int grid = sms * 4;
    const int maxg = (nGroups + (NTHREADS / 32) - 1) / (NTHREADS / 32);
    if (grid > maxg) grid = maxg;

    edgehead_mma<<<grid, NTHREADS>>>(h, ep, gamma, beta, W1, b1, W2, b2,
                                     out, E, nGroups);
}

// round 14
// speedup vs baseline: 1.1182x; 1.1140x over previous
#include <cuda_runtime.h>
#include <cuda_fp16.h>
#include <stdint.h>

// EdgeHead via warp-level mma.sync (HMMA fp16): M=16/warp, 5 CTAs/SM
// (20 warps — R11's proven balance point), raw-feature A operand (R12's
// instruction savings).
// LN folded OUT of the GEMM:  sum_k z_k W'_kj = rs*(sum_k feat_k W'_kj)
//                                             - rs*mu*(sum_k W'_kj)
// A = [u, v, |u-v|, u*v] raw fp16 (u,v stored half2; d,p one op per t),
// affine (rs, rs*mu, colsum, bc) applied per-column in fp32 epilogue.
// B = (gamma.*W1)^T fp16 smem, k-permuted + XOR-swizzled.
// bc = beta @ W1 + b1, colsum_j = sum_k gamma_k W1_kj.

#define NTHREADS 128
typedef unsigned long long u64;

__device__ __forceinline__ u64 pk2(float x, float y) {
    u64 r; asm("mov.b64 %0, {%1, %2};" : "=l"(r) : "f"(x), "f"(y)); return r;
}
__device__ __forceinline__ void upk2(u64 a, float& x, float& y) {
    asm("mov.b64 {%0, %1}, %2;" : "=f"(x), "=f"(y) : "l"(a));
}
__device__ __forceinline__ u64 fma2(u64 a, u64 b, u64 c) {
    u64 r; asm("fma.rn.f32x2 %0, %1, %2, %3;" : "=l"(r) : "l"(a), "l"(b), "l"(c));
    return r;
}
__device__ __forceinline__ u64 add2(u64 a, u64 b) {
    u64 r; asm("add.rn.f32x2 %0, %1, %2;" : "=l"(r) : "l"(a), "l"(b)); return r;
}
__device__ __forceinline__ u64 mul2(u64 a, u64 b) {
    u64 r; asm("mul.rn.f32x2 %0, %1, %2;" : "=l"(r) : "l"(a), "l"(b)); return r;
}
#define ABS2MASK 0x7fffffff7fffffffULL

__device__ __forceinline__ uint32_t pack_h2(float x, float y) {
    __half2 t = __floats2half2_rn(x, y);   // .x = low half
    uint32_t r; memcpy(&r, &t, 4); return r;
}
__device__ __forceinline__ __half2 u2h(uint32_t u) {
    __half2 t; memcpy(&t, &u, 4); return t;
}
__device__ __forceinline__ uint32_t h2u(__half2 h) {
    uint32_t r; memcpy(&r, &h, 4); return r;
}

__device__ __forceinline__ void mma16816(float* c, uint32_t a0, uint32_t a1,
                                         uint32_t a2, uint32_t a3,
                                         uint32_t b0, uint32_t b1) {
    asm volatile(
        "mma.sync.aligned.m16n8k16.row.col.f32.f16.f16.f32 "
        "{%0,%1,%2,%3}, {%4,%5,%6,%7}, {%8,%9}, {%0,%1,%2,%3};"
        : "+f"(c[0]), "+f"(c[1]), "+f"(c[2]), "+f"(c[3])
        : "r"(a0), "r"(a1), "r"(a2), "r"(a3), "r"(b0), "r"(b1));
}

__device__ __forceinline__ void ldsm4(uint32_t addr, uint32_t& r0, uint32_t& r1,
                                      uint32_t& r2, uint32_t& r3) {
    asm volatile("ldmatrix.sync.aligned.m8n8.x4.shared.b16 {%0,%1,%2,%3}, [%4];"
                 : "=r"(r0), "=r"(r1), "=r"(r2), "=r"(r3) : "r"(addr));
}

// stats accumulate for one packed (u,v) pair into S1,S2 (fp32 exact)
__device__ __forceinline__ void statacc(u64 uu, u64 vv, u64 neg1,
                                        u64& S1, u64& S2) {
    const u64 p = mul2(uu, vv);
    const u64 d = fma2(vv, neg1, uu) & ABS2MASK;
    S1 = add2(S1, add2(uu, vv));
    S1 = add2(S1, add2(d, p));
    S2 = fma2(uu, uu, S2); S2 = fma2(vv, vv, S2);
    S2 = fma2(d, d, S2);   S2 = fma2(p, p, S2);
}

__global__ __launch_bounds__(NTHREADS, 5)
void edgehead_mma(const float* __restrict__ h,
                  const void* __restrict__ ep_raw,
                  const float* __restrict__ gamma,
                  const float* __restrict__ beta,
                  const float* __restrict__ W1,
                  const float* __restrict__ b1,
                  const float* __restrict__ W2,
                  const float* __restrict__ b2,
                  float* __restrict__ out,
                  int E, int nGroups)
{
    __shared__ __align__(128) unsigned char Bhi[16384];  // 32j x 256k fp16, swz
    __shared__ float bc_s[32], w2_s[32], cs_s[32];

    const int tid = threadIdx.x;
    const int wid = tid >> 5;
    const int lane = tid & 31;

    // ---- stage B^T = (gamma .* W1)^T fp16, k-permuted + XOR-swizzled ----
    // phys k within 16-block maps to mma col m = ((k&12)>>1) + ((k&2)?8:0)
    for (int p = tid; p < 4096; p += NTHREADS) {
        const int j = p & 31;
        const int k0 = (p >> 5) << 1;                    // even phys k
        const float w0 = gamma[k0] * W1[k0 * 32 + j];
        const float w1 = gamma[k0 + 1] * W1[(k0 + 1) * 32 + j];
        const int m0 = ((k0 & 12) >> 1) + ((k0 & 2) ? 8 : 0);
        const int kp = (k0 & ~15) + m0;                  // permuted, even
        const uint32_t off = (uint32_t)(j * 512 + ((((kp >> 3)) ^ (j & 7)) << 4)
                                        + (kp & 7) * 2);
        *(uint32_t*)(Bhi + off) = pack_h2(w0, w1);
    }
    if (tid < 32) {
        float ab = b1[tid];     // bc = beta @ W1 + b1
        float ac = 0.f;         // colsum = gamma @ W1 (columnwise)
        #pragma unroll 8
        for (int k = 0; k < 256; k++) {
            const float w = W1[k * 32 + tid];
            ab = fmaf(beta[k], w, ab);
            ac = fmaf(gamma[k], w, ac);
        }
        bc_s[tid] = ab;
        cs_s[tid] = ac;
        w2_s[tid] = W2[tid];
    }
    __syncthreads();

    // ---- edge index dtype sniff (int64 vs int32) ----
    const int* ep32 = (const int*)ep_raw;
    const long long* ep64 = (const long long*)ep_raw;
    int hiOr = 0;
    #pragma unroll
    for (int t = 1; t < 16; t += 2) hiOr |= ep32[t];
    const bool wide = (hiOr == 0);
    const float b2v = b2[0];
    const u64 neg1 = pk2(-1.f, -1.f);

    // ---- per-lane constants ----
    const int cq = lane & 3;           // quad position: owns phys dims 4cq..+3
    const int q = lane >> 2;           // edge row within group (and +8)
    const float4* __restrict__ hv4 = (const float4*)h;   // 16 float4 per node

    const int x7 = lane & 7;
    const int pday = (lane >> 3) & 1;
    const int jrow = ((lane >> 4)) * 8 + x7;
    const uint32_t bhiB = (uint32_t)__cvta_generic_to_shared(Bhi) + jrow * 512;

    const int gw = blockIdx.x * (NTHREADS / 32) + wid;
    const int gstride = gridDim.x * (NTHREADS / 32);

    for (int g = gw; g < nGroups; g += gstride) {
        const int e0 = g * 16 + q;
        const int e1 = e0 + 8;
        const bool v0 = e0 < E, v1 = e1 < E;
        int s0, d0, s1i, d1;
        if (wide) {
            s0 = v0 ? (int)ep64[e0] : 0; d0 = v0 ? (int)ep64[e0 + E] : 0;
            s1i = v1 ? (int)ep64[e1] : 0; d1 = v1 ? (int)ep64[e1 + E] : 0;
        } else {
            s0 = v0 ? ep32[e0] : 0; d0 = v0 ? ep32[e0 + E] : 0;
            s1i = v1 ? ep32[e1] : 0; d1 = v1 ? ep32[e1 + E] : 0;
        }

        // ---- gather + inline stats (fp32) + compress raws to half2 ----
        uint32_t Uh0[8], Vh0[8], Uh1[8], Vh1[8];   // 32 regs total
        u64 S1a = 0, S2a = 0, S1b = 0, S2b = 0;
        {
            const float4* pu0 = hv4 + (s0 * 16 + cq);
            const float4* pv0 = hv4 + (d0 * 16 + cq);
            const float4* pu1 = hv4 + (s1i * 16 + cq);
            const float4* pv1 = hv4 + (d1 * 16 + cq);
            #pragma unroll
            for (int t = 0; t < 4; t++) {
                const float4 a = pu0[4 * t];
                const float4 b = pv0[4 * t];
                const float4 c = pu1[4 * t];
                const float4 d = pv1[4 * t];
                statacc(pk2(a.x, a.y), pk2(b.x, b.y), neg1, S1a, S2a);
                statacc(pk2(a.z, a.w), pk2(b.z, b.w), neg1, S1a, S2a);
                statacc(pk2(c.x, c.y), pk2(d.x, d.y), neg1, S1b, S2b);
                statacc(pk2(c.z, c.w), pk2(d.z, d.w), neg1, S1b, S2b);
                Uh0[2*t] = pack_h2(a.x, a.y); Uh0[2*t+1] = pack_h2(a.z, a.w);
                Vh0[2*t] = pack_h2(b.x, b.y); Vh0[2*t+1] = pack_h2(b.z, b.w);
                Uh1[2*t] = pack_h2(c.x, c.y); Uh1[2*t+1] = pack_h2(c.z, c.w);
                Vh1[2*t] = pack_h2(d.x, d.y); Vh1[2*t+1] = pack_h2(d.z, d.w);
            }
        }
        float s1r0, s2r0, s1r1, s2r1, tx, ty;
        upk2(S1a, tx, ty); s1r0 = tx + ty;
        upk2(S2a, tx, ty); s2r0 = tx + ty;
        upk2(S1b, tx, ty); s1r1 = tx + ty;
        upk2(S2b, tx, ty); s2r1 = tx + ty;

        s1r0 += __shfl_xor_sync(0xffffffffu, s1r0, 1);
        s1r0 += __shfl_xor_sync(0xffffffffu, s1r0, 2);
        s2r0 += __shfl_xor_sync(0xffffffffu, s2r0, 1);
        s2r0 += __shfl_xor_sync(0xffffffffu, s2r0, 2);
        s1r1 += __shfl_xor_sync(0xffffffffu, s1r1, 1);
        s1r1 += __shfl_xor_sync(0xffffffffu, s1r1, 2);
        s2r1 += __shfl_xor_sync(0xffffffffu, s2r1, 1);
        s2r1 += __shfl_xor_sync(0xffffffffu, s2r1, 2);

        const float mu0 = s1r0 * (1.f / 256.f);
        const float rs0 = rsqrtf(fmaf(-mu0, mu0, s2r0 * (1.f / 256.f)) + 1e-5f);
        const float mu1 = s1r1 * (1.f / 256.f);
        const float rs1 = rsqrtf(fmaf(-mu1, mu1, s2r1 * (1.f / 256.f)) + 1e-5f);

        float acc[4][4];
        #pragma unroll
        for (int nt = 0; nt < 4; nt++)
            #pragma unroll
            for (int rr = 0; rr < 4; rr++) acc[nt][rr] = 0.f;

        // ---- mma loop: raw-feature A operands; t outer, s inner ----
        #pragma unroll
        for (int t = 0; t < 4; t++) {
            // per-t derived features (one op each, reused across s)
            const uint32_t d0l = h2u(__habs2(__hsub2(u2h(Uh0[2*t]),   u2h(Vh0[2*t]))));
            const uint32_t d0h = h2u(__habs2(__hsub2(u2h(Uh0[2*t+1]), u2h(Vh0[2*t+1]))));
            const uint32_t d1l = h2u(__habs2(__hsub2(u2h(Uh1[2*t]),   u2h(Vh1[2*t]))));
            const uint32_t d1h = h2u(__habs2(__hsub2(u2h(Uh1[2*t+1]), u2h(Vh1[2*t+1]))));
            const uint32_t p0l = h2u(__hmul2(u2h(Uh0[2*t]),   u2h(Vh0[2*t])));
            const uint32_t p0h = h2u(__hmul2(u2h(Uh0[2*t+1]), u2h(Vh0[2*t+1])));
            const uint32_t p1l = h2u(__hmul2(u2h(Uh1[2*t]),   u2h(Vh1[2*t])));
            const uint32_t p1h = h2u(__hmul2(u2h(Uh1[2*t+1]), u2h(Vh1[2*t+1])));

            #pragma unroll
            for (int s = 0; s < 4; s++) {
                const int ks = s * 4 + t;
                uint32_t a0, a1, a2, a3;   // {row q klo, row q+8 klo, row q khi, row q+8 khi}
                if (s == 0)      { a0 = Uh0[2*t]; a1 = Uh1[2*t]; a2 = Uh0[2*t+1]; a3 = Uh1[2*t+1]; }
                else if (s == 1) { a0 = Vh0[2*t]; a1 = Vh1[2*t]; a2 = Vh0[2*t+1]; a3 = Vh1[2*t+1]; }
                else if (s == 2) { a0 = d0l;      a1 = d1l;      a2 = d0h;        a3 = d1h; }
                else             { a0 = p0l;      a1 = p1l;      a2 = p0h;        a3 = p1h; }

                const uint32_t sw = (uint32_t)((((ks * 2 + pday) ^ x7)) << 4);
                uint32_t bh[8];
                ldsm4(bhiB + sw,        bh[0], bh[1], bh[2], bh[3]);   // nt 0,1
                ldsm4(bhiB + sw + 8192, bh[4], bh[5], bh[6], bh[7]);   // nt 2,3

                #pragma unroll
                for (int nt = 0; nt < 4; nt++)
                    mma16816(acc[nt], a0, a1, a2, a3, bh[2 * nt], bh[2 * nt + 1]);
            }
        }

        // ---- epilogue: LN affine + relu + W2 dot, quad reduce ----
        // hm_j = rs*acc_j - rs*mu*colsum_j + bc_j
        const float rm0 = rs0 * mu0, rm1 = rs1 * mu1;
        const int c = cq * 2;
        float pp0 = 0.f, pp1 = 0.f;
        #pragma unroll
        for (int nt = 0; nt < 4; nt++) {
            const float bcx = bc_s[nt * 8 + c], bcy = bc_s[nt * 8 + c + 1];
            const float w2x = w2_s[nt * 8 + c], w2y = w2_s[nt * 8 + c + 1];
            const float csx = cs_s[nt * 8 + c], csy = cs_s[nt * 8 + c + 1];
            pp0 = fmaf(fmaxf(fmaf(rs0, acc[nt][0], fmaf(-rm0, csx, bcx)), 0.f), w2x, pp0);
            pp0 = fmaf(fmaxf(fmaf(rs0, acc[nt][1], fmaf(-rm0, csy, bcy)), 0.f), w2y, pp0);
            pp1 = fmaf(fmaxf(fmaf(rs1, acc[nt][2], fmaf(-rm1, csx, bcx)), 0.f), w2x, pp1);
            pp1 = fmaf(fmaxf(fmaf(rs1, acc[nt][3], fmaf(-rm1, csy, bcy)), 0.f), w2y, pp1);
        }
        pp0 += __shfl_xor_sync(0xffffffffu, pp0, 1);
        pp0 += __shfl_xor_sync(0xffffffffu, pp0, 2);
        pp1 += __shfl_xor_sync(0xffffffffu, pp1, 1);
        pp1 += __shfl_xor_sync(0xffffffffu, pp1, 2);
        if (cq == 0) {
            if (v0) out[e0] = pp0 + b2v;
            if (v1) out[e1] = pp1 + b2v;
        }
    }
}

extern "C" void kernel_launch(void* const* d_in, const int* in_sizes, int n_in,
                              void* d_out, int out_size)
{
    const float* h     = (const float*)d_in[0];
    const void*  ep    = d_in[1];
    const float* gamma = (const float*)d_in[2];
    const float* beta  = (const float*)d_in[3];
    const float* W1    = (const float*)d_in[4];
    const float* b1    = (const float*)d_in[5];
    const float* W2    = (const float*)d_in[6];
    const float* b2    = (const float*)d_in[7];
    float* out = (float*)d_out;
    const int E = out_size;
    const int nGroups = (E + 15) / 16;

    int dev = 0, sms = 148;
    cudaGetDevice(&dev);
    cudaDeviceGetAttribute(&sms, cudaDevAttrMultiProcessorCount, dev);
    int grid = sms * 5;
    const int maxg = (nGroups + (NTHREADS / 32) - 1) / (NTHREADS / 32);
    if (grid > maxg) grid = maxg;

    edgehead_mma<<<grid, NTHREADS>>>(h, ep, gamma, beta, W1, b1, W2, b2,
                                     out, E, nGroups);
}

// round 15
// speedup vs baseline: 1.1351x; 1.0151x over previous
#include <cuda_runtime.h>
#include <cuda_fp16.h>
#include <stdint.h>

// EdgeHead, two-kernel scheme:
// 1) precompute_P: P_u[n] = h[n] @ (gamma.*W1)[0:64], P_v[n] = h[n] @ rows
//    64:128, fp16, stored in fragment-permuted column order (lane-contiguous).
// 2) edgehead_mma: per edge, gather u,v; fp32 LN stats; MMA only over the
//    nonlinear half K=128 ([|u-v|, u*v] vs gamma.*W1 rows 128..255); add
//    P_u[src]+P_v[dst]; apply LN affine in fp32 epilogue:
//    out = rs*(P_u+P_v+mma) - rs*mu*colsum + bc, then relu,W2,b2.
// bc = beta@W1+b1, colsum_j = sum_k gamma_k W1_kj (all 256 k).

#define NTHREADS 128
#define PCAP 131072
typedef unsigned long long u64;

__device__ __align__(16) __half Pu_g[(size_t)PCAP * 32];
__device__ __align__(16) __half Pv_g[(size_t)PCAP * 32];

__device__ __forceinline__ u64 pk2(float x, float y) {
    u64 r; asm("mov.b64 %0, {%1, %2};" : "=l"(r) : "f"(x), "f"(y)); return r;
}
__device__ __forceinline__ void upk2(u64 a, float& x, float& y) {
    asm("mov.b64 {%0, %1}, %2;" : "=f"(x), "=f"(y) : "l"(a));
}
__device__ __forceinline__ u64 fma2(u64 a, u64 b, u64 c) {
    u64 r; asm("fma.rn.f32x2 %0, %1, %2, %3;" : "=l"(r) : "l"(a), "l"(b), "l"(c));
    return r;
}
__device__ __forceinline__ u64 add2(u64 a, u64 b) {
    u64 r; asm("add.rn.f32x2 %0, %1, %2;" : "=l"(r) : "l"(a), "l"(b)); return r;
}
__device__ __forceinline__ u64 mul2(u64 a, u64 b) {
    u64 r; asm("mul.rn.f32x2 %0, %1, %2;" : "=l"(r) : "l"(a), "l"(b)); return r;
}
#define ABS2MASK 0x7fffffff7fffffffULL

__device__ __forceinline__ uint32_t pack_h2(float x, float y) {
    __half2 t = __floats2half2_rn(x, y);
    uint32_t r; memcpy(&r, &t, 4); return r;
}
__device__ __forceinline__ float2 uh2f2(uint32_t u) {
    __half2 t; memcpy(&t, &u, 4); return __half22float2(t);
}

__device__ __forceinline__ void mma16816(float* c, uint32_t a0, uint32_t a1,
                                         uint32_t a2, uint32_t a3,
                                         uint32_t b0, uint32_t b1) {
    asm volatile(
        "mma.sync.aligned.m16n8k16.row.col.f32.f16.f16.f32 "
        "{%0,%1,%2,%3}, {%4,%5,%6,%7}, {%8,%9}, {%0,%1,%2,%3};"
        : "+f"(c[0]), "+f"(c[1]), "+f"(c[2]), "+f"(c[3])
        : "r"(a0), "r"(a1), "r"(a2), "r"(a3), "r"(b0), "r"(b1));
}
__device__ __forceinline__ void ldsm4(uint32_t addr, uint32_t& r0, uint32_t& r1,
                                      uint32_t& r2, uint32_t& r3) {
    asm volatile("ldmatrix.sync.aligned.m8n8.x4.shared.b16 {%0,%1,%2,%3}, [%4];"
                 : "=r"(r0), "=r"(r1), "=r"(r2), "=r"(r3) : "r"(addr));
}

// ============================ precompute kernel ============================
__global__ __launch_bounds__(NTHREADS, 4)
void precompute_P(const float* __restrict__ h,
                  const float* __restrict__ gamma,
                  const float* __restrict__ W1,
                  int N)
{
    __shared__ __align__(128) unsigned char Bu[4096], Bv[4096];
    const int tid = threadIdx.x;
    const int wid = tid >> 5, lane = tid & 31;

    // stage Wu' (k 0..63), Wv' (k 64..127): 32j x 64k fp16, permuted+swizzled
    for (int p = tid; p < 1024; p += NTHREADS) {
        const int j = p & 31;
        const int k0 = (p >> 5) << 1;                    // even, 0..62
        const float u0 = gamma[k0]      * W1[k0 * 32 + j];
        const float u1 = gamma[k0 + 1]  * W1[(k0 + 1) * 32 + j];
        const float v0 = gamma[k0 + 64] * W1[(k0 + 64) * 32 + j];
        const float v1 = gamma[k0 + 65] * W1[(k0 + 65) * 32 + j];
        const int m0 = ((k0 & 12) >> 1) + ((k0 & 2) ? 8 : 0);
        const int kp = (k0 & ~15) + m0;
        const uint32_t off = (uint32_t)(j * 128 + (((kp >> 3) ^ (j & 7)) << 4)
                                        + (kp & 7) * 2);
        *(uint32_t*)(Bu + off) = pack_h2(u0, u1);
        *(uint32_t*)(Bv + off) = pack_h2(v0, v1);
    }
    __syncthreads();

    const int cq = lane & 3, q = lane >> 2;
    const int x7 = lane & 7, pday = (lane >> 3) & 1;
    const int jrow = ((lane >> 4)) * 8 + x7;
    const uint32_t buB = (uint32_t)__cvta_generic_to_shared(Bu) + jrow * 128;
    const uint32_t bvB = (uint32_t)__cvta_generic_to_shared(Bv) + jrow * 128;
    const float4* hv4 = (const float4*)h;

    const int nTiles = (N + 15) >> 4;
    const int w0 = blockIdx.x * 4 + wid;
    const int ws = gridDim.x * 4;
    for (int tile = w0; tile < nTiles; tile += ws) {
        const int na = tile * 16 + q;
        const int nb = na + 8;
        const int nac = na < N ? na : 0;
        const int nbc = nb < N ? nb : 0;
        uint32_t Ah[8], Ch[8];
        const float4* pa = hv4 + (nac * 16 + cq);
        const float4* pb = hv4 + (nbc * 16 + cq);
        #pragma unroll
        for (int t = 0; t < 4; t++) {
            const float4 fa = pa[4 * t];
            const float4 fb = pb[4 * t];
            Ah[2*t] = pack_h2(fa.x, fa.y); Ah[2*t+1] = pack_h2(fa.z, fa.w);
            Ch[2*t] = pack_h2(fb.x, fb.y); Ch[2*t+1] = pack_h2(fb.z, fb.w);
        }
        float au[4][4], av[4][4];
        #pragma unroll
        for (int nt = 0; nt < 4; nt++)
            #pragma unroll
            for (int r = 0; r < 4; r++) { au[nt][r] = 0.f; av[nt][r] = 0.f; }

        #pragma unroll
        for (int t = 0; t < 4; t++) {
            const uint32_t sw = (uint32_t)(((t * 2 + pday) ^ x7) << 4);
            uint32_t bu[8], bv[8];
            ldsm4(buB + sw,        bu[0], bu[1], bu[2], bu[3]);
            ldsm4(buB + sw + 2048, bu[4], bu[5], bu[6], bu[7]);
            ldsm4(bvB + sw,        bv[0], bv[1], bv[2], bv[3]);
            ldsm4(bvB + sw + 2048, bv[4], bv[5], bv[6], bv[7]);
            #pragma unroll
            for (int nt = 0; nt < 4; nt++) {
                mma16816(au[nt], Ah[2*t], Ch[2*t], Ah[2*t+1], Ch[2*t+1],
                         bu[2*nt], bu[2*nt+1]);
                mma16816(av[nt], Ah[2*t], Ch[2*t], Ah[2*t+1], Ch[2*t+1],
                         bv[2*nt], bv[2*nt+1]);
            }
        }
        // store permuted records: node row -> 8 halves at [node*32 + cq*8]
        if (na < N) {
            uint4 r;
            r.x = pack_h2(au[0][0], au[0][1]); r.y = pack_h2(au[1][0], au[1][1]);
            r.z = pack_h2(au[2][0], au[2][1]); r.w = pack_h2(au[3][0], au[3][1]);
            ((uint4*)Pu_g)[na * 4 + cq] = r;
            r.x = pack_h2(av[0][0], av[0][1]); r.y = pack_h2(av[1][0], av[1][1]);
            r.z = pack_h2(av[2][0], av[2][1]); r.w = pack_h2(av[3][0], av[3][1]);
            ((uint4*)Pv_g)[na * 4 + cq] = r;
        }
        if (nb < N) {
            uint4 r;
            r.x = pack_h2(au[0][2], au[0][3]); r.y = pack_h2(au[1][2], au[1][3]);
            r.z = pack_h2(au[2][2], au[2][3]); r.w = pack_h2(au[3][2], au[3][3]);
            ((uint4*)Pu_g)[nb * 4 + cq] = r;
            r.x = pack_h2(av[0][2], av[0][3]); r.y = pack_h2(av[1][2], av[1][3]);
            r.z = pack_h2(av[2][2], av[2][3]); r.w = pack_h2(av[3][2], av[3][3]);
            ((uint4*)Pv_g)[nb * 4 + cq] = r;
        }
    }
}

// ============================== main kernel ================================
__global__ __launch_bounds__(NTHREADS, 5)
void edgehead_mma(const float* __restrict__ h,
                  const void* __restrict__ ep_raw,
                  const float* __restrict__ gamma,
                  const float* __restrict__ beta,
                  const float* __restrict__ W1,
                  const float* __restrict__ b1,
                  const float* __restrict__ W2,
                  const float* __restrict__ b2,
                  float* __restrict__ out,
                  int E, int nGroups)
{
    __shared__ __align__(128) unsigned char Bseg[8192];  // 32j x 128k fp16, swz
    __shared__ float bc_s[32], w2_s[32], cs_s[32];

    const int tid = threadIdx.x;
    const int wid = tid >> 5;
    const int lane = tid & 31;

    // ---- stage B = (gamma .* W1) rows 128..255, k-permuted + swizzled ----
    for (int p = tid; p < 2048; p += NTHREADS) {
        const int j = p & 31;
        const int k0 = 128 + ((p >> 5) << 1);            // even, 128..254
        const float w0 = gamma[k0] * W1[k0 * 32 + j];
        const float w1 = gamma[k0 + 1] * W1[(k0 + 1) * 32 + j];
        const int bk = k0 - 128;
        const int m0 = ((bk & 12) >> 1) + ((bk & 2) ? 8 : 0);
        const int kp = (bk & ~15) + m0;                  // 0..127, even
        const uint32_t off = (uint32_t)(j * 256 + (((kp >> 3) ^ (j & 7)) << 4)
                                        + (kp & 7) * 2);
        *(uint32_t*)(Bseg + off) = pack_h2(w0, w1);
    }
    if (tid < 32) {
        float ab = b1[tid];     // bc = beta @ W1 + b1
        float ac = 0.f;         // colsum = gamma @ W1 (all 256 k)
        #pragma unroll 8
        for (int k = 0; k < 256; k++) {
            const float w = W1[k * 32 + tid];
            ab = fmaf(beta[k], w, ab);
            ac = fmaf(gamma[k], w, ac);
        }
        bc_s[tid] = ab;
        cs_s[tid] = ac;
        w2_s[tid] = W2[tid];
    }
    __syncthreads();

    // ---- edge index dtype sniff (int64 vs int32) ----
    const int* ep32 = (const int*)ep_raw;
    const long long* ep64 = (const long long*)ep_raw;
    int hiOr = 0;
    #pragma unroll
    for (int t = 1; t < 16; t += 2) hiOr |= ep32[t];
    const bool wide = (hiOr == 0);
    const float b2v = b2[0];
    const u64 neg1 = pk2(-1.f, -1.f);

    const int cq = lane & 3;
    const int q = lane >> 2;
    const float4* __restrict__ hv4 = (const float4*)h;

    const int x7 = lane & 7;
    const int pday = (lane >> 3) & 1;
    const int jrow = ((lane >> 4)) * 8 + x7;
    const uint32_t bB = (uint32_t)__cvta_generic_to_shared(Bseg) + jrow * 256;

    const uint4* __restrict__ PuT = (const uint4*)Pu_g;
    const uint4* __restrict__ PvT = (const uint4*)Pv_g;

    const int gw = blockIdx.x * (NTHREADS / 32) + wid;
    const int gstride = gridDim.x * (NTHREADS / 32);

    for (int g = gw; g < nGroups; g += gstride) {
        const int e0 = g * 16 + q;
        const int e1 = e0 + 8;
        const bool v0 = e0 < E, v1 = e1 < E;
        int s0, d0, s1i, d1;
        if (wide) {
            s0 = v0 ? (int)ep64[e0] : 0; d0 = v0 ? (int)ep64[e0 + E] : 0;
            s1i = v1 ? (int)ep64[e1] : 0; d1 = v1 ? (int)ep64[e1 + E] : 0;
        } else {
            s0 = v0 ? ep32[e0] : 0; d0 = v0 ? ep32[e0 + E] : 0;
            s1i = v1 ? ep32[e1] : 0; d1 = v1 ? ep32[e1 + E] : 0;
        }

        // ---- gather + fp32 stats; keep |u-v| and u*v as half2 ----
        uint32_t Dh0[8], Ph0[8], Dh1[8], Ph1[8];
        u64 S1a = 0, S2a = 0, S1b = 0, S2b = 0;
        {
            const float4* pu0 = hv4 + (s0 * 16 + cq);
            const float4* pv0 = hv4 + (d0 * 16 + cq);
            const float4* pu1 = hv4 + (s1i * 16 + cq);
            const float4* pv1 = hv4 + (d1 * 16 + cq);
            #pragma unroll
            for (int t = 0; t < 4; t++) {
                const float4 a = pu0[4 * t];
                const float4 b = pv0[4 * t];
                const float4 c = pu1[4 * t];
                const float4 d4 = pv1[4 * t];
                #pragma unroll
                for (int hlf = 0; hlf < 2; hlf++) {
                    {
                        const u64 uu = hlf ? pk2(a.z, a.w) : pk2(a.x, a.y);
                        const u64 vv = hlf ? pk2(b.z, b.w) : pk2(b.x, b.y);
                        const u64 prod = mul2(uu, vv);
                        const u64 dif = fma2(vv, neg1, uu) & ABS2MASK;
                        S1a = add2(S1a, add2(uu, vv));
                        S1a = add2(S1a, add2(dif, prod));
                        S2a = fma2(uu, uu, S2a); S2a = fma2(vv, vv, S2a);
                        S2a = fma2(dif, dif, S2a); S2a = fma2(prod, prod, S2a);
                        float dx, dy, px, py;
                        upk2(dif, dx, dy); upk2(prod, px, py);
                        Dh0[2*t + hlf] = pack_h2(dx, dy);
                        Ph0[2*t + hlf] = pack_h2(px, py);
                    }
                    {
                        const u64 uu = hlf ? pk2(c.z, c.w) : pk2(c.x, c.y);
                        const u64 vv = hlf ? pk2(d4.z, d4.w) : pk2(d4.x, d4.y);
                        const u64 prod = mul2(uu, vv);
                        const u64 dif = fma2(vv, neg1, uu) & ABS2MASK;
                        S1b = add2(S1b, add2(uu, vv));
                        S1b = add2(S1b, add2(dif, prod));
                        S2b = fma2(uu, uu, S2b); S2b = fma2(vv, vv, S2b);
                        S2b = fma2(dif, dif, S2b); S2b = fma2(prod, prod, S2b);
                        float dx, dy, px, py;
                        upk2(dif, dx, dy); upk2(prod, px, py);
                        Dh1[2*t + hlf] = pack_h2(dx, dy);
                        Ph1[2*t + hlf] = pack_h2(px, py);
                    }
                }
            }
        }
        float s1r0, s2r0, s1r1, s2r1, tx, ty;
        upk2(S1a, tx, ty); s1r0 = tx + ty;
        upk2(S2a, tx, ty); s2r0 = tx + ty;
        upk2(S1b, tx, ty); s1r1 = tx + ty;
        upk2(S2b, tx, ty); s2r1 = tx + ty;

        s1r0 += __shfl_xor_sync(0xffffffffu, s1r0, 1);
        s1r0 += __shfl_xor_sync(0xffffffffu, s1r0, 2);
        s2r0 += __shfl_xor_sync(0xffffffffu, s2r0, 1);
        s2r0 += __shfl_xor_sync(0xffffffffu, s2r0, 2);
        s1r1 += __shfl_xor_sync(0xffffffffu, s1r1, 1);
        s1r1 += __shfl_xor_sync(0xffffffffu, s1r1, 2);
        s2r1 += __shfl_xor_sync(0xffffffffu, s2r1, 1);
        s2r1 += __shfl_xor_sync(0xffffffffu, s2r1, 2);

        const float mu0 = s1r0 * (1.f / 256.f);
        const float rs0 = rsqrtf(fmaf(-mu0, mu0, s2r0 * (1.f / 256.f)) + 1e-5f);
        const float mu1 = s1r1 * (1.f / 256.f);
        const float rs1 = rsqrtf(fmaf(-mu1, mu1, s2r1 * (1.f / 256.f)) + 1e-5f);

        // ---- P loads (in flight during mma) ----
        const uint4 puA = PuT[s0 * 4 + cq];
        const uint4 puB = PuT[s1i * 4 + cq];
        const uint4 pvA = PvT[d0 * 4 + cq];
        const uint4 pvB = PvT[d1 * 4 + cq];

        float acc[4][4];
        #pragma unroll
        for (int nt = 0; nt < 4; nt++)
            #pragma unroll
            for (int rr = 0; rr < 4; rr++) acc[nt][rr] = 0.f;

        // ---- mma loop: K=128 (segments |u-v|, u*v) ----
        #pragma unroll
        for (int t = 0; t < 4; t++) {
            #pragma unroll
            for (int s2 = 0; s2 < 2; s2++) {
                const int ks = s2 * 4 + t;
                uint32_t a0, a1, a2, a3;
                if (s2 == 0) { a0 = Dh0[2*t]; a1 = Dh1[2*t];
                               a2 = Dh0[2*t+1]; a3 = Dh1[2*t+1]; }
                else         { a0 = Ph0[2*t]; a1 = Ph1[2*t];
                               a2 = Ph0[2*t+1]; a3 = Ph1[2*t+1]; }

                const uint32_t sw = (uint32_t)((((ks * 2 + pday) ^ x7)) << 4);
                uint32_t bh[8];
                ldsm4(bB + sw,        bh[0], bh[1], bh[2], bh[3]);
                ldsm4(bB + sw + 4096, bh[4], bh[5], bh[6], bh[7]);

                #pragma unroll
                for (int nt = 0; nt < 4; nt++)
                    mma16816(acc[nt], a0, a1, a2, a3, bh[2*nt], bh[2*nt+1]);
            }
        }

        // ---- epilogue: + P_u + P_v, LN affine, relu, W2 dot ----
        const float rm0 = rs0 * mu0, rm1 = rs1 * mu1;
        const int c = cq * 2;
        const uint32_t puAa[4] = {puA.x, puA.y, puA.z, puA.w};
        const uint32_t puBa[4] = {puB.x, puB.y, puB.z, puB.w};
        const uint32_t pvAa[4] = {pvA.x, pvA.y, pvA.z, pvA.w};
        const uint32_t pvBa[4] = {pvB.x, pvB.y, pvB.z, pvB.w};
        float pp0 = 0.f, pp1 = 0.f;
        #pragma unroll
        for (int nt = 0; nt < 4; nt++) {
            const float bcx = bc_s[nt * 8 + c], bcy = bc_s[nt * 8 + c + 1];
            const float w2x = w2_s[nt * 8 + c], w2y = w2_s[nt * 8 + c + 1];
            const float csx = cs_s[nt * 8 + c], csy = cs_s[nt * 8 + c + 1];
            const float2 xa = uh2f2(puAa[nt]), ya = uh2f2(pvAa[nt]);
            const float2 xb = uh2f2(puBa[nt]), yb = uh2f2(pvBa[nt]);
            const float t00 = acc[nt][0] + xa.x + ya.x;
            const float t01 = acc[nt][1] + xa.y + ya.y;
            const float t10 = acc[nt][2] + xb.x + yb.x;
            const float t11 = acc[nt][3] + xb.y + yb.y;
            pp0 = fmaf(fmaxf(fmaf(rs0, t00, fmaf(-rm0, csx, bcx)), 0.f), w2x, pp0);
            pp0 = fmaf(fmaxf(fmaf(rs0, t01, fmaf(-rm0, csy, bcy)), 0.f), w2y, pp0);
            pp1 = fmaf(fmaxf(fmaf(rs1, t10, fmaf(-rm1, csx, bcx)), 0.f), w2x, pp1);
            pp1 = fmaf(fmaxf(fmaf(rs1, t11, fmaf(-rm1, csy, bcy)), 0.f), w2y, pp1);
        }
        pp0 += __shfl_xor_sync(0xffffffffu, pp0, 1);
        pp0 += __shfl_xor_sync(0xffffffffu, pp0, 2);
        pp1 += __shfl_xor_sync(0xffffffffu, pp1, 1);
        pp1 += __shfl_xor_sync(0xffffffffu, pp1, 2);
        if (cq == 0) {
            if (v0) out[e0] = pp0 + b2v;
            if (v1) out[e1] = pp1 + b2v;
        }
    }
}

extern "C" void kernel_launch(void* const* d_in, const int* in_sizes, int n_in,
                              void* d_out, int out_size)
{
    const float* h     = (const float*)d_in[0];
    const void*  ep    = d_in[1];
    const float* gamma = (const float*)d_in[2];
    const float* beta  = (const float*)d_in[3];
    const float* W1    = (const float*)d_in[4];
    const float* b1    = (const float*)d_in[5];
    const float* W2    = (const float*)d_in[6];
    const float* b2    = (const float*)d_in[7];
    float* out = (float*)d_out;
    const int E = out_size;
    const int nGroups = (E + 15) / 16;
    const int N = in_sizes[0] / 64;            // nodes

    int dev = 0, sms = 148;
    cudaGetDevice(&dev);
    cudaDeviceGetAttribute(&sms, cudaDevAttrMultiProcessorCount, dev);

    // 1) per-node linear-term precompute (same stream -> ordered)
    const int nTiles = (N + 15) / 16;
    int pg = (nTiles + 3) / 4;
    if (pg > sms * 4) pg = sms * 4;
    precompute_P<<<pg, NTHREADS>>>(h, gamma, W1, N);

    // 2) main edge kernel
    int grid = sms * 5;
    const int maxg = (nGroups + (NTHREADS / 32) - 1) / (NTHREADS / 32);
    if (grid > maxg) grid = maxg;
    edgehead_mma<<<grid, NTHREADS>>>(h, ep, gamma, beta, W1, b1, W2, b2,
                                     out, E, nGroups);
}

// round 16
// speedup vs baseline: 1.1719x; 1.0324x over previous
#include <cuda_runtime.h>
#include <cuda_fp16.h>
#include <stdint.h>

// EdgeHead, two-kernel scheme (R15 + fp16 h-copy gather):
// 1) precompute_P: P_u[n] = h[n] @ (gamma.*W1)[0:64], P_v[n] = rows 64:128
//    (fp16, fragment-permuted), AND h16[n] = fp16 copy of h[n] (identity
//    layout, 128B/node = ONE L1 line).
// 2) edgehead_mma: gather u,v from h16 (2 LDG.128/row instead of 4 — lane
//    owns 8-contiguous-dim chunks; loaded half2 words ARE the mma fragments
//    under a re-derived B k-permutation). fp32 LN stats from cvt'd values;
//    MMA K=128 over [|u-v|, u*v]; add P_u[src]+P_v[dst]; LN affine epilogue:
//    out = relu(rs*(P+mma) - rs*mu*colsum + bc) @ W2 + b2.

#define NTHREADS 128
#define PCAP 131072
typedef unsigned long long u64;

__device__ __align__(16) __half Pu_g[(size_t)PCAP * 32];
__device__ __align__(16) __half Pv_g[(size_t)PCAP * 32];
__device__ __align__(16) __half h16_g[(size_t)PCAP * 64];

__device__ __forceinline__ u64 pk2(float x, float y) {
    u64 r; asm("mov.b64 %0, {%1, %2};" : "=l"(r) : "f"(x), "f"(y)); return r;
}
__device__ __forceinline__ void upk2(u64 a, float& x, float& y) {
    asm("mov.b64 {%0, %1}, %2;" : "=f"(x), "=f"(y) : "l"(a));
}
__device__ __forceinline__ u64 fma2(u64 a, u64 b, u64 c) {
    u64 r; asm("fma.rn.f32x2 %0, %1, %2, %3;" : "=l"(r) : "l"(a), "l"(b), "l"(c));
    return r;
}
__device__ __forceinline__ u64 add2(u64 a, u64 b) {
    u64 r; asm("add.rn.f32x2 %0, %1, %2;" : "=l"(r) : "l"(a), "l"(b)); return r;
}
__device__ __forceinline__ u64 mul2(u64 a, u64 b) {
    u64 r; asm("mul.rn.f32x2 %0, %1, %2;" : "=l"(r) : "l"(a), "l"(b)); return r;
}
#define ABS2MASK 0x7fffffff7fffffffULL

__device__ __forceinline__ uint32_t pack_h2(float x, float y) {
    __half2 t = __floats2half2_rn(x, y);
    uint32_t r; memcpy(&r, &t, 4); return r;
}
__device__ __forceinline__ float2 uh2f2(uint32_t u) {
    __half2 t; memcpy(&t, &u, 4); return __half22float2(t);
}
// half2 word -> packed f32x2
__device__ __forceinline__ u64 h2tof2(uint32_t u) {
    const float2 f = uh2f2(u);
    return pk2(f.x, f.y);
}

__device__ __forceinline__ void mma16816(float* c, uint32_t a0, uint32_t a1,
                                         uint32_t a2, uint32_t a3,
                                         uint32_t b0, uint32_t b1) {
    asm volatile(
        "mma.sync.aligned.m16n8k16.row.col.f32.f16.f16.f32 "
        "{%0,%1,%2,%3}, {%4,%5,%6,%7}, {%8,%9}, {%0,%1,%2,%3};"
        : "+f"(c[0]), "+f"(c[1]), "+f"(c[2]), "+f"(c[3])
        : "r"(a0), "r"(a1), "r"(a2), "r"(a3), "r"(b0), "r"(b1));
}
__device__ __forceinline__ void ldsm4(uint32_t addr, uint32_t& r0, uint32_t& r1,
                                      uint32_t& r2, uint32_t& r3) {
    asm volatile("ldmatrix.sync.aligned.m8n8.x4.shared.b16 {%0,%1,%2,%3}, [%4];"
                 : "=r"(r0), "=r"(r1), "=r"(r2), "=r"(r3) : "r"(addr));
}

// ============================ precompute kernel ============================
__global__ __launch_bounds__(NTHREADS, 4)
void precompute_P(const float* __restrict__ h,
                  const float* __restrict__ gamma,
                  const float* __restrict__ W1,
                  int N)
{
    __shared__ __align__(128) unsigned char Bu[4096], Bv[4096];
    const int tid = threadIdx.x;
    const int wid = tid >> 5, lane = tid & 31;

    // stage Wu' (k 0..63), Wv' (k 64..127): OLD permutation (A frags from
    // fp32 loads with 4-dim-chunk ownership)
    for (int p = tid; p < 1024; p += NTHREADS) {
        const int j = p & 31;
        const int k0 = (p >> 5) << 1;
        const float u0 = gamma[k0]      * W1[k0 * 32 + j];
        const float u1 = gamma[k0 + 1]  * W1[(k0 + 1) * 32 + j];
        const float v0 = gamma[k0 + 64] * W1[(k0 + 64) * 32 + j];
        const float v1 = gamma[k0 + 65] * W1[(k0 + 65) * 32 + j];
        const int m0 = ((k0 & 12) >> 1) + ((k0 & 2) ? 8 : 0);
        const int kp = (k0 & ~15) + m0;
        const uint32_t off = (uint32_t)(j * 128 + (((kp >> 3) ^ (j & 7)) << 4)
                                        + (kp & 7) * 2);
        *(uint32_t*)(Bu + off) = pack_h2(u0, u1);
        *(uint32_t*)(Bv + off) = pack_h2(v0, v1);
    }
    __syncthreads();

    const int cq = lane & 3, q = lane >> 2;
    const int x7 = lane & 7, pday = (lane >> 3) & 1;
    const int jrow = ((lane >> 4)) * 8 + x7;
    const uint32_t buB = (uint32_t)__cvta_generic_to_shared(Bu) + jrow * 128;
    const uint32_t bvB = (uint32_t)__cvta_generic_to_shared(Bv) + jrow * 128;
    const float4* hv4 = (const float4*)h;

    const int nTiles = (N + 15) >> 4;
    const int w0 = blockIdx.x * 4 + wid;
    const int ws = gridDim.x * 4;
    for (int tile = w0; tile < nTiles; tile += ws) {
        const int na = tile * 16 + q;
        const int nb = na + 8;
        const int nac = na < N ? na : 0;
        const int nbc = nb < N ? nb : 0;
        uint32_t Ah[8], Ch[8];
        const float4* pa = hv4 + (nac * 16 + cq);
        const float4* pb = hv4 + (nbc * 16 + cq);
        #pragma unroll
        for (int t = 0; t < 4; t++) {
            const float4 fa = pa[4 * t];
            const float4 fb = pb[4 * t];
            Ah[2*t] = pack_h2(fa.x, fa.y); Ah[2*t+1] = pack_h2(fa.z, fa.w);
            Ch[2*t] = pack_h2(fb.x, fb.y); Ch[2*t+1] = pack_h2(fb.z, fb.w);
            // h16 identity-layout stores: dims 16t+4cq..+3 at byte 32t+8cq
            if (na < N) {
                uint2 r; r.x = Ah[2*t]; r.y = Ah[2*t+1];
                *(uint2*)((char*)h16_g + (size_t)na * 128 + 32 * t + 8 * cq) = r;
            }
            if (nb < N) {
                uint2 r; r.x = Ch[2*t]; r.y = Ch[2*t+1];
                *(uint2*)((char*)h16_g + (size_t)nb * 128 + 32 * t + 8 * cq) = r;
            }
        }
        float au[4][4], av[4][4];
        #pragma unroll
        for (int nt = 0; nt < 4; nt++)
            #pragma unroll
            for (int r = 0; r < 4; r++) { au[nt][r] = 0.f; av[nt][r] = 0.f; }

        #pragma unroll
        for (int t = 0; t < 4; t++) {
            const uint32_t sw = (uint32_t)(((t * 2 + pday) ^ x7) << 4);
            uint32_t bu[8], bv[8];
            ldsm4(buB + sw,        bu[0], bu[1], bu[2], bu[3]);
            ldsm4(buB + sw + 2048, bu[4], bu[5], bu[6], bu[7]);
            ldsm4(bvB + sw,        bv[0], bv[1], bv[2], bv[3]);
            ldsm4(bvB + sw + 2048, bv[4], bv[5], bv[6], bv[7]);
            #pragma unroll
            for (int nt = 0; nt < 4; nt++) {
                mma16816(au[nt], Ah[2*t], Ch[2*t], Ah[2*t+1], Ch[2*t+1],
                         bu[2*nt], bu[2*nt+1]);
                mma16816(av[nt], Ah[2*t], Ch[2*t], Ah[2*t+1], Ch[2*t+1],
                         bv[2*nt], bv[2*nt+1]);
            }
        }
        if (na < N) {
            uint4 r;
            r.x = pack_h2(au[0][0], au[0][1]); r.y = pack_h2(au[1][0], au[1][1]);
            r.z = pack_h2(au[2][0], au[2][1]); r.w = pack_h2(au[3][0], au[3][1]);
            ((uint4*)Pu_g)[na * 4 + cq] = r;
            r.x = pack_h2(av[0][0], av[0][1]); r.y = pack_h2(av[1][0], av[1][1]);
            r.z = pack_h2(av[2][0], av[2][1]); r.w = pack_h2(av[3][0], av[3][1]);
            ((uint4*)Pv_g)[na * 4 + cq] = r;
        }
        if (nb < N) {
            uint4 r;
            r.x = pack_h2(au[0][2], au[0][3]); r.y = pack_h2(au[1][2], au[1][3]);
            r.z = pack_h2(au[2][2], au[2][3]); r.w = pack_h2(au[3][2], au[3][3]);
            ((uint4*)Pu_g)[nb * 4 + cq] = r;
            r.x = pack_h2(av[0][2], av[0][3]); r.y = pack_h2(av[1][2], av[1][3]);
            r.z = pack_h2(av[2][2], av[2][3]); r.w = pack_h2(av[3][2], av[3][3]);
            ((uint4*)Pv_g)[nb * 4 + cq] = r;
        }
    }
}

// ============================== main kernel ================================
// NEW lane ownership: lane cq reads node dims [8cq..8cq+7] and [32+8cq..+7]
// (2x LDG.128). Loaded half2 word j (0..7 across both uint4s) = fragment
// index 2t+hlf. Matching B permutation for phys dim d in 0..63:
//   t = 2*(d>=32) + ((d&7)>>2),  m = 2*((d&31)>>3) + (d&1) + 8*((d>>1)&1)
__global__ __launch_bounds__(NTHREADS, 5)
void edgehead_mma(const void* __restrict__ ep_raw,
                  const float* __restrict__ gamma,
                  const float* __restrict__ beta,
                  const float* __restrict__ W1,
                  const float* __restrict__ b1,
                  const float* __restrict__ W2,
                  const float* __restrict__ b2,
                  float* __restrict__ out,
                  int E, int nGroups)
{
    __shared__ __align__(128) unsigned char Bseg[8192];  // 32j x 128k fp16, swz
    __shared__ float bc_s[32], w2_s[32], cs_s[32];

    const int tid = threadIdx.x;
    const int wid = tid >> 5;
    const int lane = tid & 31;

    // ---- stage B = (gamma .* W1) rows 128..255, NEW perm + swizzled ----
    for (int p = tid; p < 2048; p += NTHREADS) {
        const int j = p & 31;
        const int bk = (p >> 5) << 1;                    // even, 0..126
        const int k0 = 128 + bk;
        const float w0 = gamma[k0] * W1[k0 * 32 + j];
        const float w1 = gamma[k0 + 1] * W1[(k0 + 1) * 32 + j];
        const int seg = bk >> 6;
        const int d = bk & 63;
        const int i = d & 7;
        const int t = ((d >> 5) << 1) + (i >> 2);
        const int m = 2 * ((d & 31) >> 3) + 8 * ((i >> 1) & 1);  // d even
        const int kpos = (seg * 4 + t) * 16 + m;
        const uint32_t off = (uint32_t)(j * 256 + (((kpos >> 3) ^ (j & 7)) << 4)
                                        + (kpos & 7) * 2);
        *(uint32_t*)(Bseg + off) = pack_h2(w0, w1);
    }
    if (tid < 32) {
        float ab = b1[tid];     // bc = beta @ W1 + b1
        float ac = 0.f;         // colsum = gamma @ W1 (all 256 k)
        #pragma unroll 8
        for (int k = 0; k < 256; k++) {
            const float w = W1[k * 32 + tid];
            ab = fmaf(beta[k], w, ab);
            ac = fmaf(gamma[k], w, ac);
        }
        bc_s[tid] = ab;
        cs_s[tid] = ac;
        w2_s[tid] = W2[tid];
    }
    __syncthreads();

    // ---- edge index dtype sniff (int64 vs int32) ----
    const int* ep32 = (const int*)ep_raw;
    const long long* ep64 = (const long long*)ep_raw;
    int hiOr = 0;
    #pragma unroll
    for (int t = 1; t < 16; t += 2) hiOr |= ep32[t];
    const bool wide = (hiOr == 0);
    const float b2v = b2[0];
    const u64 neg1 = pk2(-1.f, -1.f);

    const int cq = lane & 3;
    const int q = lane >> 2;

    const int x7 = lane & 7;
    const int pday = (lane >> 3) & 1;
    const int jrow = ((lane >> 4)) * 8 + x7;
    const uint32_t bB = (uint32_t)__cvta_generic_to_shared(Bseg) + jrow * 256;

    const uint4* __restrict__ PuT = (const uint4*)Pu_g;
    const uint4* __restrict__ PvT = (const uint4*)Pv_g;
    const uint4* __restrict__ h16v = (const uint4*)h16_g;  // 8 uint4/node

    const int gw = blockIdx.x * (NTHREADS / 32) + wid;
    const int gstride = gridDim.x * (NTHREADS / 32);

    for (int g = gw; g < nGroups; g += gstride) {
        const int e0 = g * 16 + q;
        const int e1 = e0 + 8;
        const bool v0 = e0 < E, v1 = e1 < E;
        int s0, d0, s1i, d1;
        if (wide) {
            s0 = v0 ? (int)ep64[e0] : 0; d0 = v0 ? (int)ep64[e0 + E] : 0;
            s1i = v1 ? (int)ep64[e1] : 0; d1 = v1 ? (int)ep64[e1 + E] : 0;
        } else {
            s0 = v0 ? ep32[e0] : 0; d0 = v0 ? ep32[e0 + E] : 0;
            s1i = v1 ? ep32[e1] : 0; d1 = v1 ? ep32[e1 + E] : 0;
        }

        // ---- fp16 gather: 2 LDG.128 per node row ----
        uint32_t U0[8], V0[8], U1[8], V1[8];
        {
            uint4 a0 = h16v[s0 * 8 + cq],      a1 = h16v[s0 * 8 + 4 + cq];
            uint4 b0 = h16v[d0 * 8 + cq],      b1u = h16v[d0 * 8 + 4 + cq];
            uint4 c0 = h16v[s1i * 8 + cq],     c1 = h16v[s1i * 8 + 4 + cq];
            uint4 e0u = h16v[d1 * 8 + cq],     e1u = h16v[d1 * 8 + 4 + cq];
            U0[0]=a0.x; U0[1]=a0.y; U0[2]=a0.z; U0[3]=a0.w;
            U0[4]=a1.x; U0[5]=a1.y; U0[6]=a1.z; U0[7]=a1.w;
            V0[0]=b0.x; V0[1]=b0.y; V0[2]=b0.z; V0[3]=b0.w;
            V0[4]=b1u.x; V0[5]=b1u.y; V0[6]=b1u.z; V0[7]=b1u.w;
            U1[0]=c0.x; U1[1]=c0.y; U1[2]=c0.z; U1[3]=c0.w;
            U1[4]=c1.x; U1[5]=c1.y; U1[6]=c1.z; U1[7]=c1.w;
            V1[0]=e0u.x; V1[1]=e0u.y; V1[2]=e0u.z; V1[3]=e0u.w;
            V1[4]=e1u.x; V1[5]=e1u.y; V1[6]=e1u.z; V1[7]=e1u.w;
        }

        // ---- fp32 stats + D/P fragments ----
        uint32_t Dh0[8], Ph0[8], Dh1[8], Ph1[8];
        u64 S1a = 0, S2a = 0, S1b = 0, S2b = 0;
        #pragma unroll
        for (int j = 0; j < 8; j++) {
            {
                const u64 uu = h2tof2(U0[j]);
                const u64 vv = h2tof2(V0[j]);
                const u64 prod = mul2(uu, vv);
                const u64 dif = fma2(vv, neg1, uu) & ABS2MASK;
                S1a = add2(S1a, add2(uu, vv));
                S1a = add2(S1a, add2(dif, prod));
                S2a = fma2(uu, uu, S2a); S2a = fma2(vv, vv, S2a);
                S2a = fma2(dif, dif, S2a); S2a = fma2(prod, prod, S2a);
                float dx, dy, px, py;
                upk2(dif, dx, dy); upk2(prod, px, py);
                Dh0[j] = pack_h2(dx, dy);
                Ph0[j] = pack_h2(px, py);
            }
            {
                const u64 uu = h2tof2(U1[j]);
                const u64 vv = h2tof2(V1[j]);
                const u64 prod = mul2(uu, vv);
                const u64 dif = fma2(vv, neg1, uu) & ABS2MASK;
                S1b = add2(S1b, add2(uu, vv));
                S1b = add2(S1b, add2(dif, prod));
                S2b = fma2(uu, uu, S2b); S2b = fma2(vv, vv, S2b);
                S2b = fma2(dif, dif, S2b); S2b = fma2(prod, prod, S2b);
                float dx, dy, px, py;
                upk2(dif, dx, dy); upk2(prod, px, py);
                Dh1[j] = pack_h2(dx, dy);
                Ph1[j] = pack_h2(px, py);
            }
        }
        float s1r0, s2r0, s1r1, s2r1, tx, ty;
        upk2(S1a, tx, ty); s1r0 = tx + ty;
        upk2(S2a, tx, ty); s2r0 = tx + ty;
        upk2(S1b, tx, ty); s1r1 = tx + ty;
        upk2(S2b, tx, ty); s2r1 = tx + ty;

        s1r0 += __shfl_xor_sync(0xffffffffu, s1r0, 1);
        s1r0 += __shfl_xor_sync(0xffffffffu, s1r0, 2);
        s2r0 += __shfl_xor_sync(0xffffffffu, s2r0, 1);
        s2r0 += __shfl_xor_sync(0xffffffffu, s2r0, 2);
        s1r1 += __shfl_xor_sync(0xffffffffu, s1r1, 1);
        s1r1 += __shfl_xor_sync(0xffffffffu, s1r1, 2);
        s2r1 += __shfl_xor_sync(0xffffffffu, s2r1, 1);
        s2r1 += __shfl_xor_sync(0xffffffffu, s2r1, 2);

        const float mu0 = s1r0 * (1.f / 256.f);
        const float rs0 = rsqrtf(fmaf(-mu0, mu0, s2r0 * (1.f / 256.f)) + 1e-5f);
        const float mu1 = s1r1 * (1.f / 256.f);
        const float rs1 = rsqrtf(fmaf(-mu1, mu1, s2r1 * (1.f / 256.f)) + 1e-5f);

        // ---- P loads (in flight during mma) ----
        const uint4 puA = PuT[s0 * 4 + cq];
        const uint4 puB = PuT[s1i * 4 + cq];
        const uint4 pvA = PvT[d0 * 4 + cq];
        const uint4 pvB = PvT[d1 * 4 + cq];

        float acc[4][4];
        #pragma unroll
        for (int nt = 0; nt < 4; nt++)
            #pragma unroll
            for (int rr = 0; rr < 4; rr++) acc[nt][rr] = 0.f;

        // ---- mma loop: K=128 (segments |u-v|, u*v) ----
        #pragma unroll
        for (int t = 0; t < 4; t++) {
            #pragma unroll
            for (int s2 = 0; s2 < 2; s2++) {
                const int ks = s2 * 4 + t;
                uint32_t a0, a1, a2, a3;
                if (s2 == 0) { a0 = Dh0[2*t]; a1 = Dh1[2*t];
                               a2 = Dh0[2*t+1]; a3 = Dh1[2*t+1]; }
                else         { a0 = Ph0[2*t]; a1 = Ph1[2*t];
                               a2 = Ph0[2*t+1]; a3 = Ph1[2*t+1]; }

                const uint32_t sw = (uint32_t)((((ks * 2 + pday) ^ x7)) << 4);
                uint32_t bh[8];
                ldsm4(bB + sw,        bh[0], bh[1], bh[2], bh[3]);
                ldsm4(bB + sw + 4096, bh[4], bh[5], bh[6], bh[7]);

                #pragma unroll
                for (int nt = 0; nt < 4; nt++)
                    mma16816(acc[nt], a0, a1, a2, a3, bh[2*nt], bh[2*nt+1]);
            }
        }

        // ---- epilogue: + P_u + P_v, LN affine, relu, W2 dot ----
        const float rm0 = rs0 * mu0, rm1 = rs1 * mu1;
        const int c = cq * 2;
        const uint32_t puAa[4] = {puA.x, puA.y, puA.z, puA.w};
        const uint32_t puBa[4] = {puB.x, puB.y, puB.z, puB.w};
        const uint32_t pvAa[4] = {pvA.x, pvA.y, pvA.z, pvA.w};
        const uint32_t pvBa[4] = {pvB.x, pvB.y, pvB.z, pvB.w};
        float pp0 = 0.f, pp1 = 0.f;
        #pragma unroll
        for (int nt = 0; nt < 4; nt++) {
            const float bcx = bc_s[nt * 8 + c], bcy = bc_s[nt * 8 + c + 1];
            const float w2x = w2_s[nt * 8 + c], w2y = w2_s[nt * 8 + c + 1];
            const float csx = cs_s[nt * 8 + c], csy = cs_s[nt * 8 + c + 1];
            const float2 xa = uh2f2(puAa[nt]), ya = uh2f2(pvAa[nt]);
            const float2 xb = uh2f2(puBa[nt]), yb = uh2f2(pvBa[nt]);
            const float t00 = acc[nt][0] + xa.x + ya.x;
            const float t01 = acc[nt][1] + xa.y + ya.y;
            const float t10 = acc[nt][2] + xb.x + yb.x;
            const float t11 = acc[nt][3] + xb.y + yb.y;
            pp0 = fmaf(fmaxf(fmaf(rs0, t00, fmaf(-rm0, csx, bcx)), 0.f), w2x, pp0);
            pp0 = fmaf(fmaxf(fmaf(rs0, t01, fmaf(-rm0, csy, bcy)), 0.f), w2y, pp0);
            pp1 = fmaf(fmaxf(fmaf(rs1, t10, fmaf(-rm1, csx, bcx)), 0.f), w2x, pp1);
            pp1 = fmaf(fmaxf(fmaf(rs1, t11, fmaf(-rm1, csy, bcy)), 0.f), w2y, pp1);
        }
        pp0 += __shfl_xor_sync(0xffffffffu, pp0, 1);
        pp0 += __shfl_xor_sync(0xffffffffu, pp0, 2);
        pp1 += __shfl_xor_sync(0xffffffffu, pp1, 1);
        pp1 += __shfl_xor_sync(0xffffffffu, pp1, 2);
        if (cq == 0) {
            if (v0) out[e0] = pp0 + b2v;
            if (v1) out[e1] = pp1 + b2v;
        }
    }
}

extern "C" void kernel_launch(void* const* d_in, const int* in_sizes, int n_in,
                              void* d_out, int out_size)
{
    const float* h     = (const float*)d_in[0];
    const void*  ep    = d_in[1];
    const float* gamma = (const float*)d_in[2];
    const float* beta  = (const float*)d_in[3];
    const float* W1    = (const float*)d_in[4];
    const float* b1    = (const float*)d_in[5];
    const float* W2    = (const float*)d_in[6];
    const float* b2    = (const float*)d_in[7];
    float* out = (float*)d_out;
    const int E = out_size;
    const int nGroups = (E + 15) / 16;
    const int N = in_sizes[0] / 64;            // nodes

    int dev = 0, sms = 148;
    cudaGetDevice(&dev);
    cudaDeviceGetAttribute(&sms, cudaDevAttrMultiProcessorCount, dev);

    // 1) per-node precompute: P_u, P_v, h16 (same stream -> ordered)
    const int nTiles = (N + 15) / 16;
    int pg = (nTiles + 3) / 4;
    if (pg > sms * 4) pg = sms * 4;
    precompute_P<<<pg, NTHREADS>>>(h, gamma, W1, N);

    // 2) main edge kernel
    int grid = sms * 5;
    const int maxg = (nGroups + (NTHREADS / 32) - 1) / (NTHREADS / 32);
    if (grid > maxg) grid = maxg;
    edgehead_mma<<<grid, NTHREADS>>>(ep, gamma, beta, W1, b1, W2, b2,
                                     out, E, nGroups);
}